// round 13
// baseline (speedup 1.0000x reference)
#include <cuda_runtime.h>
#include <cuda_fp16.h>
#include <cstddef>
#include <cstdint>

#define G    20000
#define BSZ  256
#define NNZ  640000
#define H1   1024
#define H2   128
#define NCLS 33
#define CAP  128

// GEMM1 tiling
#define BM 128
#define BN 128
#define BK 32
#define ZSPLIT 25
#define KC 800
#define LDM 136
#define LDH 40

#define EMB_BLOCKS 5000
#define BKT_BLOCKS 1250

// ---------------- scratch ----------------
__device__ __half d_hsh[(size_t)G * BSZ];
__device__ __half d_hth[(size_t)G * BSZ];
__device__ __half d_tah[(size_t)G * BSZ];
__device__ __half d_tbh[(size_t)G * BSZ];
__device__ __half d_P16[(size_t)G * BSZ];

__device__ int   d_cnt[2][G];
__device__ uint2 d_ce [2][(size_t)G * CAP];

__device__ float d_part[(size_t)ZSPLIT * BSZ * H1];
__device__ float d_h1[(size_t)BSZ * H1];

// ---------------- zero counters ----------------
__global__ void k_zero() {
    int i = blockIdx.x * 256 + threadIdx.x;
    if (i < 2 * G) ((int*)d_cnt)[i] = 0;
}

// ---------------- fused embed + bucket-CSR build ----------------
__global__ void k_embed_bucket(const float* __restrict__ xs_in, const float* __restrict__ xt_in,
                               const float* __restrict__ em, const float* __restrict__ bm,
                               const float* __restrict__ ee, const float* __restrict__ be,
                               const int* __restrict__ r0, const int* __restrict__ c0, const float* __restrict__ v0,
                               const int* __restrict__ r1, const int* __restrict__ c1, const float* __restrict__ v1) {
    __shared__ float s0[32][33];
    __shared__ float s1[32][33];
    int bid = blockIdx.x;
    int tid = threadIdx.x;

    if (bid < EMB_BLOCKS) {
        int tx = tid & 31, ty = tid >> 5;
        int g0 = (bid % 625) * 32;
        int b0 = (bid / 625) * 32;
        const float EM = em[0], BM_ = bm[0], EE = ee[0], BE = be[0];
#pragma unroll
        for (int r = 0; r < 4; r++) {
            size_t idx = (size_t)(b0 + ty + r * 8) * G + g0 + tx;
            s0[ty + r * 8][tx] = xs_in[idx];
            s1[ty + r * 8][tx] = xt_in[idx];
        }
        __syncthreads();
#pragma unroll
        for (int r = 0; r < 4; r++) {
            int g = g0 + ty + r * 8;
            int b = b0 + tx;
            size_t idx = (size_t)g * BSZ + b;
            float vs = fmaxf(fmaf(EM, s0[tx][ty + r * 8], BM_), 0.f);
            float vt = fmaxf(fmaf(EE, s1[tx][ty + r * 8], BE), 0.f);
            d_hsh[idx] = __float2half_rn(vs);
            d_hth[idx] = __float2half_rn(vt);
        }
    } else {
        const int Q = NNZ / 4;
        int i = (bid - EMB_BLOCKS) * 256 + tid;
        int m;
        int4 r, c;
        float4 v;
        if (i < Q) {
            m = 0;
            r = ((const int4*)r0)[i];
            c = ((const int4*)c0)[i];
            v = ((const float4*)v0)[i];
        } else {
            m = 1;
            r = ((const int4*)r1)[i - Q];
            c = ((const int4*)c1)[i - Q];
            v = ((const float4*)v1)[i - Q];
        }
        int* cnt = d_cnt[m];
        uint2* ce = d_ce[m];
        int p0 = atomicAdd(&cnt[r.x], 1);
        int p1 = atomicAdd(&cnt[r.y], 1);
        int p2 = atomicAdd(&cnt[r.z], 1);
        int p3 = atomicAdd(&cnt[r.w], 1);
        if (p0 < CAP) ce[(size_t)r.x * CAP + p0] = make_uint2((unsigned)c.x, __float_as_uint(0.9f * v.x));
        if (p1 < CAP) ce[(size_t)r.y * CAP + p1] = make_uint2((unsigned)c.y, __float_as_uint(0.9f * v.y));
        if (p2 < CAP) ce[(size_t)r.z * CAP + p2] = make_uint2((unsigned)c.z, __float_as_uint(0.9f * v.z));
        if (p3 < CAP) ce[(size_t)r.w * CAP + p3] = make_uint2((unsigned)c.w, __float_as_uint(0.9f * v.w));
    }
}

// ---------------- SpMM: HFMA2 4-bank accumulation ----------------
// banks[k][i]: bank k (j mod 4), half2 slot i (8 halves per lane)
struct HB { __half2 b[4][4]; };

__device__ __forceinline__ void hb_zero(HB& h) {
#pragma unroll
    for (int k = 0; k < 4; k++)
#pragma unroll
        for (int i = 0; i < 4; i++)
            h.b[k][i] = __floats2half2_rn(0.f, 0.f);
}

__device__ __forceinline__ void hb_fma(HB& h, int bank, __half2 v, uint4 p) {
    const __half2* hp = (const __half2*)&p;
#pragma unroll
    for (int i = 0; i < 4; i++)
        h.b[bank][i] = __hfma2(v, hp[i], h.b[bank][i]);
}

struct F8 { float4 a, b; };

// combine 4 fp16 banks in fp32
__device__ __forceinline__ F8 hb_combine(const HB& h) {
    float r[8];
#pragma unroll
    for (int i = 0; i < 4; i++) {
        float2 f0 = __half22float2(h.b[0][i]);
        float2 f1 = __half22float2(h.b[1][i]);
        float2 f2 = __half22float2(h.b[2][i]);
        float2 f3 = __half22float2(h.b[3][i]);
        r[i * 2 + 0] = (f0.x + f1.x) + (f2.x + f3.x);
        r[i * 2 + 1] = (f0.y + f1.y) + (f2.y + f3.y);
    }
    F8 o;
    o.a = make_float4(r[0], r[1], r[2], r[3]);
    o.b = make_float4(r[4], r[5], r[6], r[7]);
    return o;
}

__device__ __forceinline__ F8 spmm_row_h(const uint2* __restrict__ ce,
                                         const uint4* __restrict__ x8,
                                         int s, int e, int cq) {
    HB h;
    hb_zero(h);
    int j = s;
    for (; j + 3 < e; j += 4) {
        uint2 e0 = ce[j], e1 = ce[j + 1], e2 = ce[j + 2], e3 = ce[j + 3];
        uint4 p0 = x8[(size_t)e0.x * 32 + cq];
        uint4 p1 = x8[(size_t)e1.x * 32 + cq];
        uint4 p2 = x8[(size_t)e2.x * 32 + cq];
        uint4 p3 = x8[(size_t)e3.x * 32 + cq];
        float f0 = __uint_as_float(e0.y), f1 = __uint_as_float(e1.y);
        float f2 = __uint_as_float(e2.y), f3 = __uint_as_float(e3.y);
        hb_fma(h, 0, __floats2half2_rn(f0, f0), p0);
        hb_fma(h, 1, __floats2half2_rn(f1, f1), p1);
        hb_fma(h, 2, __floats2half2_rn(f2, f2), p2);
        hb_fma(h, 3, __floats2half2_rn(f3, f3), p3);
    }
    int k = 0;
    for (; j < e; j++, k++) {
        uint2 e0 = ce[j];
        uint4 p0 = x8[(size_t)e0.x * 32 + cq];
        float f0 = __uint_as_float(e0.y);
        hb_fma(h, k, __floats2half2_rn(f0, f0), p0);
    }
    return hb_combine(h);
}

__device__ __forceinline__ uint4 f8_to_h8(const F8& v) {
    __half2 h0 = __floats2half2_rn(v.a.x, v.a.y);
    __half2 h1 = __floats2half2_rn(v.a.z, v.a.w);
    __half2 h2 = __floats2half2_rn(v.b.x, v.b.y);
    __half2 h3 = __floats2half2_rn(v.b.z, v.b.w);
    uint4 o;
    o.x = *reinterpret_cast<uint32_t*>(&h0);
    o.y = *reinterpret_cast<uint32_t*>(&h1);
    o.z = *reinterpret_cast<uint32_t*>(&h2);
    o.w = *reinterpret_cast<uint32_t*>(&h3);
    return o;
}

// phase 0: both matrices, 8 rows/CTA (1 warp/row)
__global__ void __launch_bounds__(256, 5) k_spmm0() {
    int tid = threadIdx.x;
    int gr = blockIdx.x * 8 + (tid >> 5);
    int cq = tid & 31;
    int m = (gr >= G) ? 1 : 0;
    int r = gr - m * G;
    const uint4* x8 = (const uint4*)(m ? d_hth : d_hsh);
    __half* yh = m ? d_tbh : d_tah;

    int s = r * CAP;
    int cnt = d_cnt[m][r];
    if (cnt > CAP) cnt = CAP;
    F8 acc = spmm_row_h(d_ce[m], x8, s, s + cnt, cq);
    ((uint4*)yh)[(size_t)r * 32 + cq] = f8_to_h8(acc);
}

// phase 1 + alpha-restart + hadamard -> d_P16 [G][B] fp16
__global__ void __launch_bounds__(256, 5) k_spmm_final() {
    int tid = threadIdx.x;
    int r = blockIdx.x * 8 + (tid >> 5);
    int cq = tid & 31;

    int c0 = d_cnt[0][r]; if (c0 > CAP) c0 = CAP;
    int c1 = d_cnt[1][r]; if (c1 > CAP) c1 = CAP;
    F8 as = spmm_row_h(d_ce[0], (const uint4*)d_tah, r * CAP, r * CAP + c0, cq);
    F8 at = spmm_row_h(d_ce[1], (const uint4*)d_tbh, r * CAP, r * CAP + c1, cq);

    uint4 hp = ((const uint4*)d_hsh)[(size_t)r * 32 + cq];
    uint4 tp = ((const uint4*)d_hth)[(size_t)r * 32 + cq];
    F8 hs, ht;
    {
        float2 f0 = __half22float2(*(const __half2*)&hp.x);
        float2 f1 = __half22float2(*(const __half2*)&hp.y);
        float2 f2 = __half22float2(*(const __half2*)&hp.z);
        float2 f3 = __half22float2(*(const __half2*)&hp.w);
        hs.a = make_float4(f0.x, f0.y, f1.x, f1.y);
        hs.b = make_float4(f2.x, f2.y, f3.x, f3.y);
        float2 g0 = __half22float2(*(const __half2*)&tp.x);
        float2 g1 = __half22float2(*(const __half2*)&tp.y);
        float2 g2 = __half22float2(*(const __half2*)&tp.z);
        float2 g3 = __half22float2(*(const __half2*)&tp.w);
        ht.a = make_float4(g0.x, g0.y, g1.x, g1.y);
        ht.b = make_float4(g2.x, g2.y, g3.x, g3.y);
    }
    F8 p;
    p.a.x = (as.a.x + 0.1f * hs.a.x) * (at.a.x + 0.1f * ht.a.x);
    p.a.y = (as.a.y + 0.1f * hs.a.y) * (at.a.y + 0.1f * ht.a.y);
    p.a.z = (as.a.z + 0.1f * hs.a.z) * (at.a.z + 0.1f * ht.a.z);
    p.a.w = (as.a.w + 0.1f * hs.a.w) * (at.a.w + 0.1f * ht.a.w);
    p.b.x = (as.b.x + 0.1f * hs.b.x) * (at.b.x + 0.1f * ht.b.x);
    p.b.y = (as.b.y + 0.1f * hs.b.y) * (at.b.y + 0.1f * ht.b.y);
    p.b.z = (as.b.z + 0.1f * hs.b.z) * (at.b.z + 0.1f * ht.b.z);
    p.b.w = (as.b.w + 0.1f * hs.b.w) * (at.b.w + 0.1f * ht.b.w);

    ((uint4*)d_P16)[(size_t)r * 32 + cq] = f8_to_h8(p);
}

// ---------------- GEMM1: fp16 mma.sync, double-buffered ----------------
__device__ __forceinline__ void mma_f16(float& c0, float& c1, float& c2, float& c3,
                                        uint32_t a0, uint32_t a1, uint32_t a2, uint32_t a3,
                                        uint32_t b0, uint32_t b1) {
    asm volatile(
        "mma.sync.aligned.m16n8k16.row.col.f32.f16.f16.f32 "
        "{%0,%1,%2,%3},{%4,%5,%6,%7},{%8,%9},{%0,%1,%2,%3};"
        : "+f"(c0), "+f"(c1), "+f"(c2), "+f"(c3)
        : "r"(a0), "r"(a1), "r"(a2), "r"(a3), "r"(b0), "r"(b1));
}

__device__ __forceinline__ void ldsm4(uint32_t& r0, uint32_t& r1, uint32_t& r2, uint32_t& r3,
                                      uint32_t addr) {
    asm volatile("ldmatrix.sync.aligned.m8n8.x4.shared.b16 {%0,%1,%2,%3},[%4];"
                 : "=r"(r0), "=r"(r1), "=r"(r2), "=r"(r3) : "r"(addr));
}

__device__ __forceinline__ void ldsm4t(uint32_t& r0, uint32_t& r1, uint32_t& r2, uint32_t& r3,
                                       uint32_t addr) {
    asm volatile("ldmatrix.sync.aligned.m8n8.x4.trans.shared.b16 {%0,%1,%2,%3},[%4];"
                 : "=r"(r0), "=r"(r1), "=r"(r2), "=r"(r3) : "r"(addr));
}

#define ASZ (BK * LDM)
#define BSZH (BN * LDH)

__global__ void __launch_bounds__(256) k_gemm1(const float* __restrict__ W1) {
    __shared__ __half As[2][ASZ];
    __shared__ __half Bs[2][BSZH];
    const int m0 = blockIdx.x * BM;
    const int n0 = blockIdx.y * BN;
    const int kbase = blockIdx.z * KC;
    const int tid = threadIdx.x;
    const int lane = tid & 31;
    const int wid = tid >> 5;
    const int wm = (wid >> 2) * 64;
    const int wn = (wid & 3) * 32;
    const int gid = lane >> 2;
    const int tig = lane & 3;

    const int akrow = tid >> 3;
    const int amseg = (tid & 7) * 16;
    const int srow = tid >> 1;
    const int shalf = tid & 1;

    const __half* __restrict__ A = d_P16;
    uint4 ra[2];
    float4 rb[4];
    float acc[4][4][4];
#pragma unroll
    for (int i = 0; i < 4; i++)
#pragma unroll
        for (int j = 0; j < 4; j++)
#pragma unroll
            for (int q = 0; q < 4; q++) acc[i][j][q] = 0.f;

    const size_t abase = (size_t)(kbase + akrow) * BSZ + m0 + amseg;
    const size_t bbase = (size_t)(n0 + srow) * G + kbase + shalf * 16;

    const int aoff = akrow * LDM + amseg;
    const int boff = srow * LDH + shalf * 16;

    const uint32_t as_smem = (uint32_t)__cvta_generic_to_shared(&As[0][0]);
    const uint32_t bs_smem = (uint32_t)__cvta_generic_to_shared(&Bs[0][0]);
    const uint32_t a_lm0 = as_smem +
        (uint32_t)((((lane & 7) + ((lane >> 4) & 1) * 8) * LDM + wm + ((lane >> 3) & 1) * 8) * 2);
    const uint32_t b_lm0 = bs_smem + (uint32_t)(((wn + (lane & 7) + (lane >> 4) * 8) * LDH
                                                 + ((lane >> 3) & 1) * 8) * 2);

    ra[0] = *(const uint4*)&A[abase];
    ra[1] = *(const uint4*)&A[abase + 8];
#pragma unroll
    for (int p = 0; p < 4; p++)
        rb[p] = *(const float4*)&W1[bbase + p * 4];
    *(uint4*)&As[0][aoff]     = ra[0];
    *(uint4*)&As[0][aoff + 8] = ra[1];
    {
        __half2 h[8];
        h[0] = __floats2half2_rn(rb[0].x, rb[0].y);
        h[1] = __floats2half2_rn(rb[0].z, rb[0].w);
        h[2] = __floats2half2_rn(rb[1].x, rb[1].y);
        h[3] = __floats2half2_rn(rb[1].z, rb[1].w);
        h[4] = __floats2half2_rn(rb[2].x, rb[2].y);
        h[5] = __floats2half2_rn(rb[2].z, rb[2].w);
        h[6] = __floats2half2_rn(rb[3].x, rb[3].y);
        h[7] = __floats2half2_rn(rb[3].z, rb[3].w);
        *(uint4*)&Bs[0][boff]     = *(uint4*)&h[0];
        *(uint4*)&Bs[0][boff + 8] = *(uint4*)&h[4];
    }
    __syncthreads();

    const int NSTAGE = KC / BK;
    for (int s = 0; s < NSTAGE; s++) {
        const int cur = s & 1;
        if (s + 1 < NSTAGE) {
            size_t ao = abase + (size_t)(s + 1) * BK * BSZ;
            size_t bo = bbase + (size_t)(s + 1) * BK;
            ra[0] = *(const uint4*)&A[ao];
            ra[1] = *(const uint4*)&A[ao + 8];
#pragma unroll
            for (int p = 0; p < 4; p++)
                rb[p] = *(const float4*)&W1[bo + p * 4];
        }
        const uint32_t a_lm = a_lm0 + cur * (ASZ * 2);
        const uint32_t b_lm = b_lm0 + cur * (BSZH * 2);
#pragma unroll
        for (int ks = 0; ks < 2; ks++) {
            uint32_t af[4][4], bf[4][2];
#pragma unroll
            for (int i = 0; i < 4; i++)
                ldsm4t(af[i][0], af[i][1], af[i][2], af[i][3],
                       a_lm + (uint32_t)((ks * 16 * LDM + i * 16) * 2));
            ldsm4(bf[0][0], bf[0][1], bf[1][0], bf[1][1],
                  b_lm + (uint32_t)((ks * 16) * 2));
            ldsm4(bf[2][0], bf[2][1], bf[3][0], bf[3][1],
                  b_lm + (uint32_t)((16 * LDH + ks * 16) * 2));
#pragma unroll
            for (int i = 0; i < 4; i++)
#pragma unroll
                for (int j = 0; j < 4; j++)
                    mma_f16(acc[i][j][0], acc[i][j][1], acc[i][j][2], acc[i][j][3],
                            af[i][0], af[i][1], af[i][2], af[i][3],
                            bf[j][0], bf[j][1]);
        }
        if (s + 1 < NSTAGE) {
            const int nxt = cur ^ 1;
            *(uint4*)&As[nxt][aoff]     = ra[0];
            *(uint4*)&As[nxt][aoff + 8] = ra[1];
            __half2 h[8];
            h[0] = __floats2half2_rn(rb[0].x, rb[0].y);
            h[1] = __floats2half2_rn(rb[0].z, rb[0].w);
            h[2] = __floats2half2_rn(rb[1].x, rb[1].y);
            h[3] = __floats2half2_rn(rb[1].z, rb[1].w);
            h[4] = __floats2half2_rn(rb[2].x, rb[2].y);
            h[5] = __floats2half2_rn(rb[2].z, rb[2].w);
            h[6] = __floats2half2_rn(rb[3].x, rb[3].y);
            h[7] = __floats2half2_rn(rb[3].z, rb[3].w);
            *(uint4*)&Bs[nxt][boff]     = *(uint4*)&h[0];
            *(uint4*)&Bs[nxt][boff + 8] = *(uint4*)&h[4];
            __syncthreads();
        }
    }

    float* out = d_part + (size_t)blockIdx.z * BSZ * H1;
#pragma unroll
    for (int i = 0; i < 4; i++) {
        int row = m0 + wm + i * 16 + gid;
#pragma unroll
        for (int j = 0; j < 4; j++) {
            int col = n0 + wn + j * 8 + 2 * tig;
            float2 lo = make_float2(acc[i][j][0], acc[i][j][1]);
            float2 hi = make_float2(acc[i][j][2], acc[i][j][3]);
            *(float2*)&out[(size_t)row * H1 + col] = lo;
            *(float2*)&out[(size_t)(row + 8) * H1 + col] = hi;
        }
    }
}

// ---------------- reduce (full grid) ----------------
__global__ void k_reduce1(const float* __restrict__ b1) {
    int i = blockIdx.x * blockDim.x + threadIdx.x;
    int n = i & (H1 - 1);
    float s = b1[n];
#pragma unroll
    for (int z = 0; z < ZSPLIT; z++)
        s += d_part[(size_t)z * BSZ * H1 + i];
    d_h1[i] = fmaxf(s, 0.f);
}

// ---------------- GEMM2 + GEMM3 fused ----------------
__global__ void k_gemm23(const float* __restrict__ W2, const float* __restrict__ b2,
                         const float* __restrict__ W3, const float* __restrict__ b3,
                         float* __restrict__ out) {
    __shared__ float sh[4][H1];
    __shared__ float h2sm[4][132];
    int b0 = blockIdx.x * 4;
    int n = threadIdx.x;
#pragma unroll
    for (int r = 0; r < 4; r++)
        for (int k = n; k < H1; k += H2)
            sh[r][k] = d_h1[(size_t)(b0 + r) * H1 + k];
    __syncthreads();
    float bias = b2[n];
    float a0 = bias, a1 = bias, a2 = bias, a3 = bias;
    const float4* w = (const float4*)(W2 + (size_t)n * H1);
#pragma unroll 4
    for (int kk = 0; kk < H1 / 4; kk++) {
        float4 wv = w[kk];
        a0 = fmaf(wv.x, sh[0][kk * 4 + 0], a0); a0 = fmaf(wv.y, sh[0][kk * 4 + 1], a0);
        a0 = fmaf(wv.z, sh[0][kk * 4 + 2], a0); a0 = fmaf(wv.w, sh[0][kk * 4 + 3], a0);
        a1 = fmaf(wv.x, sh[1][kk * 4 + 0], a1); a1 = fmaf(wv.y, sh[1][kk * 4 + 1], a1);
        a1 = fmaf(wv.z, sh[1][kk * 4 + 2], a1); a1 = fmaf(wv.w, sh[1][kk * 4 + 3], a1);
        a2 = fmaf(wv.x, sh[2][kk * 4 + 0], a2); a2 = fmaf(wv.y, sh[2][kk * 4 + 1], a2);
        a2 = fmaf(wv.z, sh[2][kk * 4 + 2], a2); a2 = fmaf(wv.w, sh[2][kk * 4 + 3], a2);
        a3 = fmaf(wv.x, sh[3][kk * 4 + 0], a3); a3 = fmaf(wv.y, sh[3][kk * 4 + 1], a3);
        a3 = fmaf(wv.z, sh[3][kk * 4 + 2], a3); a3 = fmaf(wv.w, sh[3][kk * 4 + 3], a3);
    }
    h2sm[0][n] = fmaxf(a0, 0.f);
    h2sm[1][n] = fmaxf(a1, 0.f);
    h2sm[2][n] = fmaxf(a2, 0.f);
    h2sm[3][n] = fmaxf(a3, 0.f);
    __syncthreads();

    int rb = n & 3;
    int cls = n >> 2;
#pragma unroll 1
    for (int pass = 0; pass < 2; pass++) {
        int c = cls + pass * 32;
        if (pass == 1) { c = 32; rb = n; }
        if (pass == 1 && n >= 4) break;
        float acc = b3[c];
        const float4* w3 = (const float4*)(W3 + (size_t)c * H2);
        const float4* hv = (const float4*)h2sm[rb];
#pragma unroll 8
        for (int k = 0; k < H2 / 4; k++) {
            float4 wv = w3[k];
            float4 h = hv[k];
            acc = fmaf(wv.x, h.x, acc); acc = fmaf(wv.y, h.y, acc);
            acc = fmaf(wv.z, h.z, acc); acc = fmaf(wv.w, h.w, acc);
        }
        out[(size_t)(b0 + rb) * NCLS + c] = acc;
    }
}

// ---------------- launch ----------------
extern "C" void kernel_launch(void* const* d_in, const int* in_sizes, int n_in,
                              void* d_out, int out_size) {
    const float* x_sample  = (const float*)d_in[0];
    const float* x_TF      = (const float*)d_in[1];
    const int*   adj_rows  = (const int*)  d_in[2];
    const int*   adj_cols  = (const int*)  d_in[3];
    const float* adj_vals  = (const float*)d_in[4];
    const int*   adjT_rows = (const int*)  d_in[5];
    const int*   adjT_cols = (const int*)  d_in[6];
    const float* adjT_vals = (const float*)d_in[7];
    const float* emb_mut   = (const float*)d_in[8];
    const float* bias_mut  = (const float*)d_in[9];
    const float* emb_exp   = (const float*)d_in[10];
    const float* bias_exp  = (const float*)d_in[11];
    const float* W1        = (const float*)d_in[12];
    const float* b1        = (const float*)d_in[13];
    const float* W2        = (const float*)d_in[14];
    const float* b2        = (const float*)d_in[15];
    const float* W3        = (const float*)d_in[16];
    const float* b3        = (const float*)d_in[17];
    float* out = (float*)d_out;

    k_zero<<<(2 * G + 255) / 256, 256>>>();
    k_embed_bucket<<<EMB_BLOCKS + BKT_BLOCKS, 256>>>(x_sample, x_TF,
                                                     emb_mut, bias_mut, emb_exp, bias_exp,
                                                     adj_rows, adj_cols, adj_vals,
                                                     adjT_rows, adjT_cols, adjT_vals);
    k_spmm0<<<2 * G / 8, 256>>>();
    k_spmm_final<<<G / 8, 256>>>();
    k_gemm1<<<dim3(BSZ / BM, H1 / BN, ZSPLIT), 256>>>(W1);
    k_reduce1<<<(BSZ * H1) / 256, 256>>>(b1);
    k_gemm23<<<BSZ / 4, H2>>>(W2, b2, W3, b3, out);
}

// round 14
// speedup vs baseline: 1.1015x; 1.1015x over previous
#include <cuda_runtime.h>
#include <cuda_fp16.h>
#include <cstddef>
#include <cstdint>

#define G    20000
#define BSZ  256
#define NNZ  640000
#define H1   1024
#define H2   128
#define NCLS 33
#define CAP  128

// GEMM1 tiling
#define BM 128
#define BN 128
#define BK 32
#define ZSPLIT 25
#define KC 800
#define LDM 136
#define LDH 40

#define EMB_BLOCKS 5000
#define BKT_BLOCKS 1250

// ---------------- scratch ----------------
__device__ __half d_hsh[(size_t)G * BSZ];
__device__ __half d_hth[(size_t)G * BSZ];
__device__ __half d_tah[(size_t)G * BSZ];
__device__ __half d_tbh[(size_t)G * BSZ];
__device__ __half d_P16[(size_t)G * BSZ];

__device__ int   d_cnt[2][G];
__device__ uint2 d_ce [2][(size_t)G * CAP];

__device__ float d_part[(size_t)ZSPLIT * BSZ * H1];
__device__ float d_h1[(size_t)BSZ * H1];

// ---------------- zero counters ----------------
__global__ void k_zero() {
    int i = blockIdx.x * 256 + threadIdx.x;
    if (i < 2 * G) ((int*)d_cnt)[i] = 0;
}

// ---------------- fused embed + bucket-CSR build ----------------
__global__ void k_embed_bucket(const float* __restrict__ xs_in, const float* __restrict__ xt_in,
                               const float* __restrict__ em, const float* __restrict__ bm,
                               const float* __restrict__ ee, const float* __restrict__ be,
                               const int* __restrict__ r0, const int* __restrict__ c0, const float* __restrict__ v0,
                               const int* __restrict__ r1, const int* __restrict__ c1, const float* __restrict__ v1) {
    __shared__ float s0[32][33];
    __shared__ float s1[32][33];
    int bid = blockIdx.x;
    int tid = threadIdx.x;

    if (bid < EMB_BLOCKS) {
        int tx = tid & 31, ty = tid >> 5;
        int g0 = (bid % 625) * 32;
        int b0 = (bid / 625) * 32;
        const float EM = em[0], BM_ = bm[0], EE = ee[0], BE = be[0];
#pragma unroll
        for (int r = 0; r < 4; r++) {
            size_t idx = (size_t)(b0 + ty + r * 8) * G + g0 + tx;
            s0[ty + r * 8][tx] = xs_in[idx];
            s1[ty + r * 8][tx] = xt_in[idx];
        }
        __syncthreads();
#pragma unroll
        for (int r = 0; r < 4; r++) {
            int g = g0 + ty + r * 8;
            int b = b0 + tx;
            size_t idx = (size_t)g * BSZ + b;
            float vs = fmaxf(fmaf(EM, s0[tx][ty + r * 8], BM_), 0.f);
            float vt = fmaxf(fmaf(EE, s1[tx][ty + r * 8], BE), 0.f);
            d_hsh[idx] = __float2half_rn(vs);
            d_hth[idx] = __float2half_rn(vt);
        }
    } else {
        const int Q = NNZ / 4;
        int i = (bid - EMB_BLOCKS) * 256 + tid;
        int m;
        int4 r, c;
        float4 v;
        if (i < Q) {
            m = 0;
            r = ((const int4*)r0)[i];
            c = ((const int4*)c0)[i];
            v = ((const float4*)v0)[i];
        } else {
            m = 1;
            r = ((const int4*)r1)[i - Q];
            c = ((const int4*)c1)[i - Q];
            v = ((const float4*)v1)[i - Q];
        }
        int* cnt = d_cnt[m];
        uint2* ce = d_ce[m];
        int p0 = atomicAdd(&cnt[r.x], 1);
        int p1 = atomicAdd(&cnt[r.y], 1);
        int p2 = atomicAdd(&cnt[r.z], 1);
        int p3 = atomicAdd(&cnt[r.w], 1);
        if (p0 < CAP) ce[(size_t)r.x * CAP + p0] = make_uint2((unsigned)c.x, __float_as_uint(0.9f * v.x));
        if (p1 < CAP) ce[(size_t)r.y * CAP + p1] = make_uint2((unsigned)c.y, __float_as_uint(0.9f * v.y));
        if (p2 < CAP) ce[(size_t)r.z * CAP + p2] = make_uint2((unsigned)c.z, __float_as_uint(0.9f * v.z));
        if (p3 < CAP) ce[(size_t)r.w * CAP + p3] = make_uint2((unsigned)c.w, __float_as_uint(0.9f * v.w));
    }
}

// ---------------- SpMM helpers ----------------
struct F8 { float4 a, b; };

__device__ __forceinline__ void fma_h4(F8& acc, float v, uint4 p) {
    float2 f0 = __half22float2(*(const __half2*)&p.x);
    float2 f1 = __half22float2(*(const __half2*)&p.y);
    float2 f2 = __half22float2(*(const __half2*)&p.z);
    float2 f3 = __half22float2(*(const __half2*)&p.w);
    acc.a.x = fmaf(v, f0.x, acc.a.x); acc.a.y = fmaf(v, f0.y, acc.a.y);
    acc.a.z = fmaf(v, f1.x, acc.a.z); acc.a.w = fmaf(v, f1.y, acc.a.w);
    acc.b.x = fmaf(v, f2.x, acc.b.x); acc.b.y = fmaf(v, f2.y, acc.b.y);
    acc.b.z = fmaf(v, f3.x, acc.b.z); acc.b.w = fmaf(v, f3.y, acc.b.w);
}

__device__ __forceinline__ void spmm_tail(const uint2* __restrict__ ce,
                                          const uint4* __restrict__ x8,
                                          int j, int e, int cq, F8& acc) {
    for (; j + 1 < e; j += 2) {
        uint2 e0 = ce[j], e1 = ce[j + 1];
        uint4 p0 = x8[(size_t)e0.x * 32 + cq];
        uint4 p1 = x8[(size_t)e1.x * 32 + cq];
        fma_h4(acc, __uint_as_float(e0.y), p0);
        fma_h4(acc, __uint_as_float(e1.y), p1);
    }
    if (j < e) {
        uint2 e0 = ce[j];
        fma_h4(acc, __uint_as_float(e0.y), x8[(size_t)e0.x * 32 + cq]);
    }
}

__device__ __forceinline__ uint4 f8_to_h8(const F8& v) {
    __half2 h0 = __floats2half2_rn(v.a.x, v.a.y);
    __half2 h1 = __floats2half2_rn(v.a.z, v.a.w);
    __half2 h2 = __floats2half2_rn(v.b.x, v.b.y);
    __half2 h3 = __floats2half2_rn(v.b.z, v.b.w);
    uint4 o;
    o.x = *reinterpret_cast<uint32_t*>(&h0);
    o.y = *reinterpret_cast<uint32_t*>(&h1);
    o.z = *reinterpret_cast<uint32_t*>(&h2);
    o.w = *reinterpret_cast<uint32_t*>(&h3);
    return o;
}

// phase 0: fp16 HFMA2 accumulation, dual banks (even/odd nnz), fp32 combine
__global__ void k_spmm0() {
    int tid = threadIdx.x;
    int gr = blockIdx.x * 8 + (tid >> 5);
    int cq = tid & 31;
    int m = (gr >= G) ? 1 : 0;
    int r = gr - m * G;
    const uint4* x8 = (const uint4*)(m ? d_hth : d_hsh);
    __half* yh = m ? d_tbh : d_tah;
    const uint2* __restrict__ ce = d_ce[m];

    int s = r * CAP;
    int cnt = d_cnt[m][r];
    if (cnt > CAP) cnt = CAP;
    int e = s + cnt;

    __half2 aA[4], aB[4];
#pragma unroll
    for (int i = 0; i < 4; i++) {
        aA[i] = __floats2half2_rn(0.f, 0.f);
        aB[i] = __floats2half2_rn(0.f, 0.f);
    }

    int j = s;
    for (; j + 1 < e; j += 2) {
        uint2 e0 = ce[j], e1 = ce[j + 1];
        uint4 p0 = x8[(size_t)e0.x * 32 + cq];
        uint4 p1 = x8[(size_t)e1.x * 32 + cq];
        float v0f = __uint_as_float(e0.y);
        float v1f = __uint_as_float(e1.y);
        __half2 v0 = __floats2half2_rn(v0f, v0f);
        __half2 v1 = __floats2half2_rn(v1f, v1f);
        const __half2* h0 = (const __half2*)&p0;
        const __half2* h1 = (const __half2*)&p1;
#pragma unroll
        for (int i = 0; i < 4; i++) {
            aA[i] = __hfma2(v0, h0[i], aA[i]);
            aB[i] = __hfma2(v1, h1[i], aB[i]);
        }
    }
    if (j < e) {
        uint2 e0 = ce[j];
        uint4 p0 = x8[(size_t)e0.x * 32 + cq];
        float v0f = __uint_as_float(e0.y);
        __half2 v0 = __floats2half2_rn(v0f, v0f);
        const __half2* h0 = (const __half2*)&p0;
#pragma unroll
        for (int i = 0; i < 4; i++)
            aA[i] = __hfma2(v0, h0[i], aA[i]);
    }

    uint4 o;
    uint32_t* op = (uint32_t*)&o;
#pragma unroll
    for (int i = 0; i < 4; i++) {
        float2 fa = __half22float2(aA[i]);
        float2 fb = __half22float2(aB[i]);
        __half2 hv = __floats2half2_rn(fa.x + fb.x, fa.y + fb.y);
        op[i] = *reinterpret_cast<uint32_t*>(&hv);
    }
    ((uint4*)yh)[(size_t)r * 32 + cq] = o;
}

// phase 1 + alpha-restart + hadamard -> d_P16 [G][B] fp16
// both matrices' gather streams interleaved (MLP=8), fp32 accumulation
__global__ void k_spmm_final() {
    int tid = threadIdx.x;
    int r = blockIdx.x * 8 + (tid >> 5);
    int cq = tid & 31;

    const uint2* __restrict__ ce0 = d_ce[0];
    const uint2* __restrict__ ce1 = d_ce[1];
    const uint4* __restrict__ xa = (const uint4*)d_tah;
    const uint4* __restrict__ xb = (const uint4*)d_tbh;

    int c0 = d_cnt[0][r]; if (c0 > CAP) c0 = CAP;
    int c1 = d_cnt[1][r]; if (c1 > CAP) c1 = CAP;
    int j0 = r * CAP, e0i = j0 + c0;
    int j1 = r * CAP, e1i = j1 + c1;

    F8 as, at;
    as.a = make_float4(0.f, 0.f, 0.f, 0.f);
    as.b = make_float4(0.f, 0.f, 0.f, 0.f);
    at.a = make_float4(0.f, 0.f, 0.f, 0.f);
    at.b = make_float4(0.f, 0.f, 0.f, 0.f);

    // joint main loop: 2 entries from each matrix per iteration (4 gathers in flight)
    while (j0 + 1 < e0i && j1 + 1 < e1i) {
        uint2 a0 = ce0[j0], a1 = ce0[j0 + 1];
        uint2 b0 = ce1[j1], b1 = ce1[j1 + 1];
        uint4 pa0 = xa[(size_t)a0.x * 32 + cq];
        uint4 pa1 = xa[(size_t)a1.x * 32 + cq];
        uint4 pb0 = xb[(size_t)b0.x * 32 + cq];
        uint4 pb1 = xb[(size_t)b1.x * 32 + cq];
        fma_h4(as, __uint_as_float(a0.y), pa0);
        fma_h4(as, __uint_as_float(a1.y), pa1);
        fma_h4(at, __uint_as_float(b0.y), pb0);
        fma_h4(at, __uint_as_float(b1.y), pb1);
        j0 += 2;
        j1 += 2;
    }
    spmm_tail(ce0, xa, j0, e0i, cq, as);
    spmm_tail(ce1, xb, j1, e1i, cq, at);

    uint4 hp = ((const uint4*)d_hsh)[(size_t)r * 32 + cq];
    uint4 tp = ((const uint4*)d_hth)[(size_t)r * 32 + cq];
    F8 hs, ht;
    {
        float2 f0 = __half22float2(*(const __half2*)&hp.x);
        float2 f1 = __half22float2(*(const __half2*)&hp.y);
        float2 f2 = __half22float2(*(const __half2*)&hp.z);
        float2 f3 = __half22float2(*(const __half2*)&hp.w);
        hs.a = make_float4(f0.x, f0.y, f1.x, f1.y);
        hs.b = make_float4(f2.x, f2.y, f3.x, f3.y);
        float2 g0 = __half22float2(*(const __half2*)&tp.x);
        float2 g1 = __half22float2(*(const __half2*)&tp.y);
        float2 g2 = __half22float2(*(const __half2*)&tp.z);
        float2 g3 = __half22float2(*(const __half2*)&tp.w);
        ht.a = make_float4(g0.x, g0.y, g1.x, g1.y);
        ht.b = make_float4(g2.x, g2.y, g3.x, g3.y);
    }
    F8 p;
    p.a.x = (as.a.x + 0.1f * hs.a.x) * (at.a.x + 0.1f * ht.a.x);
    p.a.y = (as.a.y + 0.1f * hs.a.y) * (at.a.y + 0.1f * ht.a.y);
    p.a.z = (as.a.z + 0.1f * hs.a.z) * (at.a.z + 0.1f * ht.a.z);
    p.a.w = (as.a.w + 0.1f * hs.a.w) * (at.a.w + 0.1f * ht.a.w);
    p.b.x = (as.b.x + 0.1f * hs.b.x) * (at.b.x + 0.1f * ht.b.x);
    p.b.y = (as.b.y + 0.1f * hs.b.y) * (at.b.y + 0.1f * ht.b.y);
    p.b.z = (as.b.z + 0.1f * hs.b.z) * (at.b.z + 0.1f * ht.b.z);
    p.b.w = (as.b.w + 0.1f * hs.b.w) * (at.b.w + 0.1f * ht.b.w);

    ((uint4*)d_P16)[(size_t)r * 32 + cq] = f8_to_h8(p);
}

// ---------------- GEMM1: fp16 mma.sync, double-buffered ----------------
__device__ __forceinline__ void mma_f16(float& c0, float& c1, float& c2, float& c3,
                                        uint32_t a0, uint32_t a1, uint32_t a2, uint32_t a3,
                                        uint32_t b0, uint32_t b1) {
    asm volatile(
        "mma.sync.aligned.m16n8k16.row.col.f32.f16.f16.f32 "
        "{%0,%1,%2,%3},{%4,%5,%6,%7},{%8,%9},{%0,%1,%2,%3};"
        : "+f"(c0), "+f"(c1), "+f"(c2), "+f"(c3)
        : "r"(a0), "r"(a1), "r"(a2), "r"(a3), "r"(b0), "r"(b1));
}

__device__ __forceinline__ void ldsm4(uint32_t& r0, uint32_t& r1, uint32_t& r2, uint32_t& r3,
                                      uint32_t addr) {
    asm volatile("ldmatrix.sync.aligned.m8n8.x4.shared.b16 {%0,%1,%2,%3},[%4];"
                 : "=r"(r0), "=r"(r1), "=r"(r2), "=r"(r3) : "r"(addr));
}

__device__ __forceinline__ void ldsm4t(uint32_t& r0, uint32_t& r1, uint32_t& r2, uint32_t& r3,
                                       uint32_t addr) {
    asm volatile("ldmatrix.sync.aligned.m8n8.x4.trans.shared.b16 {%0,%1,%2,%3},[%4];"
                 : "=r"(r0), "=r"(r1), "=r"(r2), "=r"(r3) : "r"(addr));
}

#define ASZ (BK * LDM)
#define BSZH (BN * LDH)

__global__ void __launch_bounds__(256) k_gemm1(const float* __restrict__ W1) {
    __shared__ __half As[2][ASZ];
    __shared__ __half Bs[2][BSZH];
    const int m0 = blockIdx.x * BM;
    const int n0 = blockIdx.y * BN;
    const int kbase = blockIdx.z * KC;
    const int tid = threadIdx.x;
    const int lane = tid & 31;
    const int wid = tid >> 5;
    const int wm = (wid >> 2) * 64;
    const int wn = (wid & 3) * 32;
    const int gid = lane >> 2;
    const int tig = lane & 3;

    const int akrow = tid >> 3;
    const int amseg = (tid & 7) * 16;
    const int srow = tid >> 1;
    const int shalf = tid & 1;

    const __half* __restrict__ A = d_P16;
    uint4 ra[2];
    float4 rb[4];
    float acc[4][4][4];
#pragma unroll
    for (int i = 0; i < 4; i++)
#pragma unroll
        for (int j = 0; j < 4; j++)
#pragma unroll
            for (int q = 0; q < 4; q++) acc[i][j][q] = 0.f;

    const size_t abase = (size_t)(kbase + akrow) * BSZ + m0 + amseg;
    const size_t bbase = (size_t)(n0 + srow) * G + kbase + shalf * 16;

    const int aoff = akrow * LDM + amseg;
    const int boff = srow * LDH + shalf * 16;

    const uint32_t as_smem = (uint32_t)__cvta_generic_to_shared(&As[0][0]);
    const uint32_t bs_smem = (uint32_t)__cvta_generic_to_shared(&Bs[0][0]);
    const uint32_t a_lm0 = as_smem +
        (uint32_t)((((lane & 7) + ((lane >> 4) & 1) * 8) * LDM + wm + ((lane >> 3) & 1) * 8) * 2);
    const uint32_t b_lm0 = bs_smem + (uint32_t)(((wn + (lane & 7) + (lane >> 4) * 8) * LDH
                                                 + ((lane >> 3) & 1) * 8) * 2);

    ra[0] = *(const uint4*)&A[abase];
    ra[1] = *(const uint4*)&A[abase + 8];
#pragma unroll
    for (int p = 0; p < 4; p++)
        rb[p] = *(const float4*)&W1[bbase + p * 4];
    *(uint4*)&As[0][aoff]     = ra[0];
    *(uint4*)&As[0][aoff + 8] = ra[1];
    {
        __half2 h[8];
        h[0] = __floats2half2_rn(rb[0].x, rb[0].y);
        h[1] = __floats2half2_rn(rb[0].z, rb[0].w);
        h[2] = __floats2half2_rn(rb[1].x, rb[1].y);
        h[3] = __floats2half2_rn(rb[1].z, rb[1].w);
        h[4] = __floats2half2_rn(rb[2].x, rb[2].y);
        h[5] = __floats2half2_rn(rb[2].z, rb[2].w);
        h[6] = __floats2half2_rn(rb[3].x, rb[3].y);
        h[7] = __floats2half2_rn(rb[3].z, rb[3].w);
        *(uint4*)&Bs[0][boff]     = *(uint4*)&h[0];
        *(uint4*)&Bs[0][boff + 8] = *(uint4*)&h[4];
    }
    __syncthreads();

    const int NSTAGE = KC / BK;
    for (int s = 0; s < NSTAGE; s++) {
        const int cur = s & 1;
        if (s + 1 < NSTAGE) {
            size_t ao = abase + (size_t)(s + 1) * BK * BSZ;
            size_t bo = bbase + (size_t)(s + 1) * BK;
            ra[0] = *(const uint4*)&A[ao];
            ra[1] = *(const uint4*)&A[ao + 8];
#pragma unroll
            for (int p = 0; p < 4; p++)
                rb[p] = *(const float4*)&W1[bo + p * 4];
        }
        const uint32_t a_lm = a_lm0 + cur * (ASZ * 2);
        const uint32_t b_lm = b_lm0 + cur * (BSZH * 2);
#pragma unroll
        for (int ks = 0; ks < 2; ks++) {
            uint32_t af[4][4], bf[4][2];
#pragma unroll
            for (int i = 0; i < 4; i++)
                ldsm4t(af[i][0], af[i][1], af[i][2], af[i][3],
                       a_lm + (uint32_t)((ks * 16 * LDM + i * 16) * 2));
            ldsm4(bf[0][0], bf[0][1], bf[1][0], bf[1][1],
                  b_lm + (uint32_t)((ks * 16) * 2));
            ldsm4(bf[2][0], bf[2][1], bf[3][0], bf[3][1],
                  b_lm + (uint32_t)((16 * LDH + ks * 16) * 2));
#pragma unroll
            for (int i = 0; i < 4; i++)
#pragma unroll
                for (int j = 0; j < 4; j++)
                    mma_f16(acc[i][j][0], acc[i][j][1], acc[i][j][2], acc[i][j][3],
                            af[i][0], af[i][1], af[i][2], af[i][3],
                            bf[j][0], bf[j][1]);
        }
        if (s + 1 < NSTAGE) {
            const int nxt = cur ^ 1;
            *(uint4*)&As[nxt][aoff]     = ra[0];
            *(uint4*)&As[nxt][aoff + 8] = ra[1];
            __half2 h[8];
            h[0] = __floats2half2_rn(rb[0].x, rb[0].y);
            h[1] = __floats2half2_rn(rb[0].z, rb[0].w);
            h[2] = __floats2half2_rn(rb[1].x, rb[1].y);
            h[3] = __floats2half2_rn(rb[1].z, rb[1].w);
            h[4] = __floats2half2_rn(rb[2].x, rb[2].y);
            h[5] = __floats2half2_rn(rb[2].z, rb[2].w);
            h[6] = __floats2half2_rn(rb[3].x, rb[3].y);
            h[7] = __floats2half2_rn(rb[3].z, rb[3].w);
            *(uint4*)&Bs[nxt][boff]     = *(uint4*)&h[0];
            *(uint4*)&Bs[nxt][boff + 8] = *(uint4*)&h[4];
            __syncthreads();
        }
    }

    float* out = d_part + (size_t)blockIdx.z * BSZ * H1;
#pragma unroll
    for (int i = 0; i < 4; i++) {
        int row = m0 + wm + i * 16 + gid;
#pragma unroll
        for (int j = 0; j < 4; j++) {
            int col = n0 + wn + j * 8 + 2 * tig;
            float2 lo = make_float2(acc[i][j][0], acc[i][j][1]);
            float2 hi = make_float2(acc[i][j][2], acc[i][j][3]);
            *(float2*)&out[(size_t)row * H1 + col] = lo;
            *(float2*)&out[(size_t)(row + 8) * H1 + col] = hi;
        }
    }
}

// ---------------- reduce (full grid) ----------------
__global__ void k_reduce1(const float* __restrict__ b1) {
    int i = blockIdx.x * blockDim.x + threadIdx.x;
    int n = i & (H1 - 1);
    float s = b1[n];
#pragma unroll
    for (int z = 0; z < ZSPLIT; z++)
        s += d_part[(size_t)z * BSZ * H1 + i];
    d_h1[i] = fmaxf(s, 0.f);
}

// ---------------- GEMM2 + GEMM3 fused ----------------
__global__ void k_gemm23(const float* __restrict__ W2, const float* __restrict__ b2,
                         const float* __restrict__ W3, const float* __restrict__ b3,
                         float* __restrict__ out) {
    __shared__ float sh[4][H1];
    __shared__ float h2sm[4][132];
    int b0 = blockIdx.x * 4;
    int n = threadIdx.x;
#pragma unroll
    for (int r = 0; r < 4; r++)
        for (int k = n; k < H1; k += H2)
            sh[r][k] = d_h1[(size_t)(b0 + r) * H1 + k];
    __syncthreads();
    float bias = b2[n];
    float a0 = bias, a1 = bias, a2 = bias, a3 = bias;
    const float4* w = (const float4*)(W2 + (size_t)n * H1);
#pragma unroll 4
    for (int kk = 0; kk < H1 / 4; kk++) {
        float4 wv = w[kk];
        a0 = fmaf(wv.x, sh[0][kk * 4 + 0], a0); a0 = fmaf(wv.y, sh[0][kk * 4 + 1], a0);
        a0 = fmaf(wv.z, sh[0][kk * 4 + 2], a0); a0 = fmaf(wv.w, sh[0][kk * 4 + 3], a0);
        a1 = fmaf(wv.x, sh[1][kk * 4 + 0], a1); a1 = fmaf(wv.y, sh[1][kk * 4 + 1], a1);
        a1 = fmaf(wv.z, sh[1][kk * 4 + 2], a1); a1 = fmaf(wv.w, sh[1][kk * 4 + 3], a1);
        a2 = fmaf(wv.x, sh[2][kk * 4 + 0], a2); a2 = fmaf(wv.y, sh[2][kk * 4 + 1], a2);
        a2 = fmaf(wv.z, sh[2][kk * 4 + 2], a2); a2 = fmaf(wv.w, sh[2][kk * 4 + 3], a2);
        a3 = fmaf(wv.x, sh[3][kk * 4 + 0], a3); a3 = fmaf(wv.y, sh[3][kk * 4 + 1], a3);
        a3 = fmaf(wv.z, sh[3][kk * 4 + 2], a3); a3 = fmaf(wv.w, sh[3][kk * 4 + 3], a3);
    }
    h2sm[0][n] = fmaxf(a0, 0.f);
    h2sm[1][n] = fmaxf(a1, 0.f);
    h2sm[2][n] = fmaxf(a2, 0.f);
    h2sm[3][n] = fmaxf(a3, 0.f);
    __syncthreads();

    int rb = n & 3;
    int cls = n >> 2;
#pragma unroll 1
    for (int pass = 0; pass < 2; pass++) {
        int c = cls + pass * 32;
        if (pass == 1) { c = 32; rb = n; }
        if (pass == 1 && n >= 4) break;
        float acc = b3[c];
        const float4* w3 = (const float4*)(W3 + (size_t)c * H2);
        const float4* hv = (const float4*)h2sm[rb];
#pragma unroll 8
        for (int k = 0; k < H2 / 4; k++) {
            float4 wv = w3[k];
            float4 h = hv[k];
            acc = fmaf(wv.x, h.x, acc); acc = fmaf(wv.y, h.y, acc);
            acc = fmaf(wv.z, h.z, acc); acc = fmaf(wv.w, h.w, acc);
        }
        out[(size_t)(b0 + rb) * NCLS + c] = acc;
    }
}

// ---------------- launch ----------------
extern "C" void kernel_launch(void* const* d_in, const int* in_sizes, int n_in,
                              void* d_out, int out_size) {
    const float* x_sample  = (const float*)d_in[0];
    const float* x_TF      = (const float*)d_in[1];
    const int*   adj_rows  = (const int*)  d_in[2];
    const int*   adj_cols  = (const int*)  d_in[3];
    const float* adj_vals  = (const float*)d_in[4];
    const int*   adjT_rows = (const int*)  d_in[5];
    const int*   adjT_cols = (const int*)  d_in[6];
    const float* adjT_vals = (const float*)d_in[7];
    const float* emb_mut   = (const float*)d_in[8];
    const float* bias_mut  = (const float*)d_in[9];
    const float* emb_exp   = (const float*)d_in[10];
    const float* bias_exp  = (const float*)d_in[11];
    const float* W1        = (const float*)d_in[12];
    const float* b1        = (const float*)d_in[13];
    const float* W2        = (const float*)d_in[14];
    const float* b2        = (const float*)d_in[15];
    const float* W3        = (const float*)d_in[16];
    const float* b3        = (const float*)d_in[17];
    float* out = (float*)d_out;

    k_zero<<<(2 * G + 255) / 256, 256>>>();
    k_embed_bucket<<<EMB_BLOCKS + BKT_BLOCKS, 256>>>(x_sample, x_TF,
                                                     emb_mut, bias_mut, emb_exp, bias_exp,
                                                     adj_rows, adj_cols, adj_vals,
                                                     adjT_rows, adjT_cols, adjT_vals);
    k_spmm0<<<2 * G / 8, 256>>>();
    k_spmm_final<<<G / 8, 256>>>();
    k_gemm1<<<dim3(BSZ / BM, H1 / BN, ZSPLIT), 256>>>(W1);
    k_reduce1<<<(BSZ * H1) / 256, 256>>>(b1);
    k_gemm23<<<BSZ / 4, H2>>>(W2, b2, W3, b3, out);
}